// round 1
// baseline (speedup 1.0000x reference)
#include <cuda_runtime.h>
#include <math.h>

#define T_TOK 8192
#define D_EMB 1024
#define HID   4096
#define ADP   256
#define NEXP  8

// Scratch (device globals — allocation-free per harness rules)
__device__ __align__(16) float g_H[(size_t)T_TOK * HID];   // h, later h + 0.1*h2
__device__ __align__(16) float g_A[T_TOK * ADP];           // a = h @ W_adapt^T
__device__ __align__(16) float g_AN[T_TOK * ADP];          // a_norm
__device__ int g_route[T_TOK];

// ---------------------------------------------------------------------------
// Routing: last expert with weight > 0 (torch scatter-overwrite semantics)
// ---------------------------------------------------------------------------
__global__ void route_kernel(const float* __restrict__ ew) {
    int t = blockIdx.x * blockDim.x + threadIdx.x;
    if (t >= T_TOK) return;
    int last = -1;
#pragma unroll
    for (int e = 0; e < NEXP; e++)
        if (ew[t * NEXP + e] > 0.0f) last = e;
    g_route[t] = last;
}

// ---------------------------------------------------------------------------
// Generic NT SGEMM: C[M,N] = epilogue( A[M,K] @ B[N,K]^T )
//   MODE 0: C = silu(acc)
//   MODE 1: C = acc
//   MODE 2: C = C + 0.1f * acc   (read-modify-write)
//   MODE 3: C = acc              (plain store, used for final output)
// Tiles: BM=BN=64, BK=16; 256 threads (16x16), 4x4 micro-tile per thread.
// Requires M,N % 64 == 0 and K % 16 == 0 (holds for all shapes here).
// ---------------------------------------------------------------------------
template <int MODE>
__global__ void __launch_bounds__(256, 2)
gemm_nt(const float* __restrict__ A, const float* __restrict__ B,
        float* __restrict__ C, int M, int N, int K) {
    const int BM = 64, BN = 64, BK = 16;
    __shared__ __align__(16) float As[BK][68];  // [k][m], pad keeps 16B align
    __shared__ __align__(16) float Bs[BK][68];  // [k][n]

    const int tid  = threadIdx.y * 16 + threadIdx.x;
    const int row  = tid >> 2;   // 0..63
    const int quad = tid & 3;    // 0..3  (16 floats per row -> 4 float4)
    const int m0 = blockIdx.y * BM;
    const int n0 = blockIdx.x * BN;

    float acc[4][4] = {};

    const float* Ab = A + (size_t)(m0 + row) * K + quad * 4;
    const float* Bb = B + (size_t)(n0 + row) * K + quad * 4;

    for (int k0 = 0; k0 < K; k0 += BK) {
        float4 av = *(const float4*)(Ab + k0);
        float4 bv = *(const float4*)(Bb + k0);
        As[quad * 4 + 0][row] = av.x;
        As[quad * 4 + 1][row] = av.y;
        As[quad * 4 + 2][row] = av.z;
        As[quad * 4 + 3][row] = av.w;
        Bs[quad * 4 + 0][row] = bv.x;
        Bs[quad * 4 + 1][row] = bv.y;
        Bs[quad * 4 + 2][row] = bv.z;
        Bs[quad * 4 + 3][row] = bv.w;
        __syncthreads();

#pragma unroll
        for (int kk = 0; kk < BK; kk++) {
            float4 a = *(const float4*)&As[kk][threadIdx.y * 4];
            float4 b = *(const float4*)&Bs[kk][threadIdx.x * 4];
            float ar[4] = {a.x, a.y, a.z, a.w};
            float br[4] = {b.x, b.y, b.z, b.w};
#pragma unroll
            for (int i = 0; i < 4; i++)
#pragma unroll
                for (int j = 0; j < 4; j++)
                    acc[i][j] = fmaf(ar[i], br[j], acc[i][j]);
        }
        __syncthreads();
    }

#pragma unroll
    for (int i = 0; i < 4; i++) {
        int m = m0 + threadIdx.y * 4 + i;
        float* Crow = C + (size_t)m * N + n0 + threadIdx.x * 4;
#pragma unroll
        for (int j = 0; j < 4; j++) {
            float v = acc[i][j];
            if (MODE == 0) v = v / (1.0f + expf(-v));   // silu
            if (MODE == 2) v = Crow[j] + 0.1f * v;
            Crow[j] = v;
        }
    }
}

// ---------------------------------------------------------------------------
// Per-token expert adapter matvec (256x256) + per-expert LayerNorm.
// One block per token, 256 threads; thread o computes a_sel[o], then
// cooperative two-pass LN. Tokens with no active expert write 0 (so the
// expert branch contributes nothing downstream).
// ---------------------------------------------------------------------------
__global__ void __launch_bounds__(256)
adapter_ln_kernel(const float* __restrict__ Wexp,
                  const float* __restrict__ gamma,
                  const float* __restrict__ beta) {
    const int t = blockIdx.x;
    const int o = threadIdx.x;
    const int e = g_route[t];

    __shared__ __align__(16) float sa[ADP];
    __shared__ float red[256];

    sa[o] = g_A[t * ADP + o];
    __syncthreads();

    float acc = 0.0f;
    if (e >= 0) {
        const float4* wr = (const float4*)(Wexp + ((size_t)e * ADP + o) * ADP);
#pragma unroll 8
        for (int d4 = 0; d4 < ADP / 4; d4++) {
            float4 w = wr[d4];
            float4 a = *(const float4*)&sa[d4 * 4];
            acc = fmaf(w.x, a.x, acc);
            acc = fmaf(w.y, a.y, acc);
            acc = fmaf(w.z, a.z, acc);
            acc = fmaf(w.w, a.w, acc);
        }
    }

    // mean
    red[o] = acc;
    __syncthreads();
#pragma unroll
    for (int s = 128; s > 0; s >>= 1) {
        if (o < s) red[o] += red[o + s];
        __syncthreads();
    }
    float mu = red[0] * (1.0f / ADP);
    __syncthreads();

    // variance (two-pass for stability)
    float dv = acc - mu;
    red[o] = dv * dv;
    __syncthreads();
#pragma unroll
    for (int s = 128; s > 0; s >>= 1) {
        if (o < s) red[o] += red[o + s];
        __syncthreads();
    }
    float var = red[0] * (1.0f / ADP);
    float rs = rsqrtf(var + 1e-5f);

    float out = 0.0f;
    if (e >= 0)
        out = dv * rs * gamma[e * ADP + o] + beta[e * ADP + o];
    g_AN[t * ADP + o] = out;
}

// ---------------------------------------------------------------------------
// Launch
// ---------------------------------------------------------------------------
extern "C" void kernel_launch(void* const* d_in, const int* in_sizes, int n_in,
                              void* d_out, int out_size) {
    const float* x      = (const float*)d_in[0];  // [T, D]
    const float* ew     = (const float*)d_in[1];  // [T, E]
    const float* W_up   = (const float*)d_in[2];  // [HID, D]
    const float* W_ad   = (const float*)d_in[3];  // [ADP, HID]
    const float* W_exp  = (const float*)d_in[4];  // [E, ADP, ADP]
    const float* gamma  = (const float*)d_in[5];  // [E, ADP]
    const float* beta   = (const float*)d_in[6];  // [E, ADP]
    const float* W_ep   = (const float*)d_in[7];  // [HID, ADP]
    const float* W_out  = (const float*)d_in[8];  // [D, HID]
    float* out = (float*)d_out;                   // [T, D]

    void *pH, *pA, *pAN;
    cudaGetSymbolAddress(&pH, g_H);
    cudaGetSymbolAddress(&pA, g_A);
    cudaGetSymbolAddress(&pAN, g_AN);
    float* H  = (float*)pH;
    float* Aa = (float*)pA;
    float* AN = (float*)pAN;

    dim3 thr(16, 16);

    // 1. routing
    route_kernel<<<(T_TOK + 255) / 256, 256>>>(ew);

    // 2. H = silu(x @ W_up^T)            [T, HID], K = D
    gemm_nt<0><<<dim3(HID / 64, T_TOK / 64), thr>>>(x, W_up, H, T_TOK, HID, D_EMB);

    // 3. A = H @ W_adapt^T               [T, ADP], K = HID
    gemm_nt<1><<<dim3(ADP / 64, T_TOK / 64), thr>>>(H, W_ad, Aa, T_TOK, ADP, HID);

    // 4. per-token adapter + LayerNorm -> AN
    adapter_ln_kernel<<<T_TOK, 256>>>(W_exp, gamma, beta);

    // 5. H += 0.1 * (AN @ W_ep^T)        [T, HID], K = ADP
    gemm_nt<2><<<dim3(HID / 64, T_TOK / 64), thr>>>(AN, W_ep, H, T_TOK, HID, ADP);

    // 6. out = H @ W_out^T               [T, D], K = HID  (fused shared+expert)
    gemm_nt<3><<<dim3(D_EMB / 64, T_TOK / 64), thr>>>(H, W_out, out, T_TOK, D_EMB, HID);
}

// round 2
// speedup vs baseline: 2.7553x; 2.7553x over previous
#include <cuda_runtime.h>
#include <math.h>

#define T_TOK 8192
#define D_EMB 1024
#define HID   4096
#define ADP   256
#define NEXP  8
#define GRP   16   // tokens per adapter block

// ---------------- scratch (device globals, allocation-free) ----------------
__device__ __align__(16) float g_H[(size_t)T_TOK * HID];   // h, later h + 0.1*h2
__device__ __align__(16) float g_A[T_TOK * ADP];           // a = h @ W_adapt^T
__device__ __align__(16) float g_AN[T_TOK * ADP];          // a_norm
__device__ int g_route[T_TOK];
__device__ int g_perm[T_TOK];
__device__ int g_cnt[NEXP];
__device__ int g_cur[NEXP];
__device__ int g_off[NEXP + 1];
__device__ int g_blkoff[NEXP + 1];

// ---------------------------------------------------------------------------
// Routing / grouping
// ---------------------------------------------------------------------------
__global__ void init_kernel() {
    if (threadIdx.x < NEXP) g_cnt[threadIdx.x] = 0;
}

__global__ void route_kernel(const float* __restrict__ ew) {
    int t = blockIdx.x * blockDim.x + threadIdx.x;
    if (t >= T_TOK) return;
    int last = -1;
#pragma unroll
    for (int e = 0; e < NEXP; e++)
        if (ew[t * NEXP + e] > 0.0f) last = e;
    g_route[t] = last;
    if (last >= 0) atomicAdd(&g_cnt[last], 1);
}

__global__ void scan_kernel() {
    if (threadIdx.x == 0) {
        int off = 0, boff = 0;
        g_off[0] = 0; g_blkoff[0] = 0;
        for (int e = 0; e < NEXP; e++) {
            g_cur[e] = 0;
            off += g_cnt[e];                     g_off[e + 1] = off;
            boff += (g_cnt[e] + GRP - 1) / GRP;  g_blkoff[e + 1] = boff;
        }
    }
}

__global__ void scatter_kernel() {
    int t = blockIdx.x * blockDim.x + threadIdx.x;
    if (t >= T_TOK) return;
    int e = g_route[t];
    if (e >= 0) {
        int slot = g_off[e] + atomicAdd(&g_cur[e], 1);
        g_perm[slot] = t;
    }
}

// ---------------------------------------------------------------------------
// TF32 tensor-core NT GEMM: C[M,N] = epi( A[M,K] @ B[N,K]^T )
//   MODE 0: silu(acc)    MODE 1: acc    MODE 2: C + 0.1*acc
// BM=BN=128, BK=16, 256 threads (8 warps, 2x4), warp tile 64x32,
// mma.m16n8k8.tf32, double-buffered smem, [k][m]/[k][n] padded layout.
// Requires M%128==0, N%128==0, K%16==0.
// ---------------------------------------------------------------------------
__device__ __forceinline__ unsigned f2tf32(float x) {
    unsigned u;
    asm("cvt.rna.tf32.f32 %0, %1;" : "=r"(u) : "f"(x));
    return u;
}

__device__ __forceinline__ void mma8(float* d, const unsigned* a, const unsigned* b) {
    asm volatile(
        "mma.sync.aligned.m16n8k8.row.col.f32.tf32.tf32.f32 "
        "{%0,%1,%2,%3}, {%4,%5,%6,%7}, {%8,%9}, {%0,%1,%2,%3};\n"
        : "+f"(d[0]), "+f"(d[1]), "+f"(d[2]), "+f"(d[3])
        : "r"(a[0]), "r"(a[1]), "r"(a[2]), "r"(a[3]), "r"(b[0]), "r"(b[1]));
}

#define BM 128
#define BN 128
#define BK 16

template <int MODE>
__global__ void __launch_bounds__(256, 2)
gemm_tf32(const float* __restrict__ A, const float* __restrict__ B,
          float* __restrict__ C, int M, int N, int K) {
    __shared__ unsigned As[2][BK][BM + 8];
    __shared__ unsigned Bs[2][BK][BN + 8];

    const int tid = threadIdx.x;
    const int lane = tid & 31, warp = tid >> 5;
    const int wm = warp >> 2, wn = warp & 3;     // 2 x 4 warp grid
    const int g = lane >> 2, c = lane & 3;

    const int m0 = blockIdx.y * BM, n0 = blockIdx.x * BN;
    const int lr = tid >> 2;   // 0..63
    const int lq = tid & 3;    // k-quad

    const float* Ap = A + (size_t)(m0 + lr) * K + lq * 4;
    const float* Bp = B + (size_t)(n0 + lr) * K + lq * 4;

    float acc[4][4][4];
#pragma unroll
    for (int i = 0; i < 4; i++)
#pragma unroll
        for (int j = 0; j < 4; j++)
#pragma unroll
            for (int r = 0; r < 4; r++) acc[i][j][r] = 0.0f;

    // load tile 0
    float4 ra0 = *(const float4*)(Ap);
    float4 ra1 = *(const float4*)(Ap + (size_t)64 * K);
    float4 rb0 = *(const float4*)(Bp);
    float4 rb1 = *(const float4*)(Bp + (size_t)64 * K);
    {
        unsigned* a0 = &As[0][lq * 4][lr];
        unsigned* b0 = &Bs[0][lq * 4][lr];
        a0[0 * (BM + 8)] = f2tf32(ra0.x); a0[1 * (BM + 8)] = f2tf32(ra0.y);
        a0[2 * (BM + 8)] = f2tf32(ra0.z); a0[3 * (BM + 8)] = f2tf32(ra0.w);
        a0 += 64;
        a0[0 * (BM + 8)] = f2tf32(ra1.x); a0[1 * (BM + 8)] = f2tf32(ra1.y);
        a0[2 * (BM + 8)] = f2tf32(ra1.z); a0[3 * (BM + 8)] = f2tf32(ra1.w);
        b0[0 * (BN + 8)] = f2tf32(rb0.x); b0[1 * (BN + 8)] = f2tf32(rb0.y);
        b0[2 * (BN + 8)] = f2tf32(rb0.z); b0[3 * (BN + 8)] = f2tf32(rb0.w);
        b0 += 64;
        b0[0 * (BN + 8)] = f2tf32(rb1.x); b0[1 * (BN + 8)] = f2tf32(rb1.y);
        b0[2 * (BN + 8)] = f2tf32(rb1.z); b0[3 * (BN + 8)] = f2tf32(rb1.w);
    }
    __syncthreads();

    const int KT = K / BK;
    for (int kt = 0; kt < KT; kt++) {
        const int buf = kt & 1;
        if (kt + 1 < KT) {
            const float* Ap2 = Ap + (kt + 1) * BK;
            const float* Bp2 = Bp + (kt + 1) * BK;
            ra0 = *(const float4*)(Ap2);
            ra1 = *(const float4*)(Ap2 + (size_t)64 * K);
            rb0 = *(const float4*)(Bp2);
            rb1 = *(const float4*)(Bp2 + (size_t)64 * K);
        }

#pragma unroll
        for (int ks = 0; ks < 2; ks++) {
            const int kc0 = ks * 8 + c, kc1 = kc0 + 4;
            unsigned af[4][4], bf[4][2];
#pragma unroll
            for (int mi = 0; mi < 4; mi++) {
                int m = wm * 64 + mi * 16 + g;
                af[mi][0] = As[buf][kc0][m];
                af[mi][1] = As[buf][kc0][m + 8];
                af[mi][2] = As[buf][kc1][m];
                af[mi][3] = As[buf][kc1][m + 8];
            }
#pragma unroll
            for (int ni = 0; ni < 4; ni++) {
                int n = wn * 32 + ni * 8 + g;
                bf[ni][0] = Bs[buf][kc0][n];
                bf[ni][1] = Bs[buf][kc1][n];
            }
#pragma unroll
            for (int mi = 0; mi < 4; mi++)
#pragma unroll
                for (int ni = 0; ni < 4; ni++)
                    mma8(acc[mi][ni], af[mi], bf[ni]);
        }

        if (kt + 1 < KT) {
            const int nb = buf ^ 1;
            unsigned* a0 = &As[nb][lq * 4][lr];
            unsigned* b0 = &Bs[nb][lq * 4][lr];
            a0[0 * (BM + 8)] = f2tf32(ra0.x); a0[1 * (BM + 8)] = f2tf32(ra0.y);
            a0[2 * (BM + 8)] = f2tf32(ra0.z); a0[3 * (BM + 8)] = f2tf32(ra0.w);
            a0 += 64;
            a0[0 * (BM + 8)] = f2tf32(ra1.x); a0[1 * (BM + 8)] = f2tf32(ra1.y);
            a0[2 * (BM + 8)] = f2tf32(ra1.z); a0[3 * (BM + 8)] = f2tf32(ra1.w);
            b0[0 * (BN + 8)] = f2tf32(rb0.x); b0[1 * (BN + 8)] = f2tf32(rb0.y);
            b0[2 * (BN + 8)] = f2tf32(rb0.z); b0[3 * (BN + 8)] = f2tf32(rb0.w);
            b0 += 64;
            b0[0 * (BN + 8)] = f2tf32(rb1.x); b0[1 * (BN + 8)] = f2tf32(rb1.y);
            b0[2 * (BN + 8)] = f2tf32(rb1.z); b0[3 * (BN + 8)] = f2tf32(rb1.w);
        }
        __syncthreads();
    }

    // epilogue
#pragma unroll
    for (int mi = 0; mi < 4; mi++) {
        int row0 = m0 + wm * 64 + mi * 16 + g;
#pragma unroll
        for (int ni = 0; ni < 4; ni++) {
            int col = n0 + wn * 32 + ni * 8 + 2 * c;
            float* p0 = C + (size_t)row0 * N + col;
            float* p1 = C + (size_t)(row0 + 8) * N + col;
            float v0 = acc[mi][ni][0], v1 = acc[mi][ni][1];
            float v2 = acc[mi][ni][2], v3 = acc[mi][ni][3];
            if (MODE == 0) {
                v0 = v0 / (1.0f + __expf(-v0)); v1 = v1 / (1.0f + __expf(-v1));
                v2 = v2 / (1.0f + __expf(-v2)); v3 = v3 / (1.0f + __expf(-v3));
            }
            if (MODE == 2) {
                v0 = p0[0] + 0.1f * v0; v1 = p0[1] + 0.1f * v1;
                v2 = p1[0] + 0.1f * v2; v3 = p1[1] + 0.1f * v3;
            }
            p0[0] = v0; p0[1] = v1;
            p1[0] = v2; p1[1] = v3;
        }
    }
}

// ---------------------------------------------------------------------------
// Grouped adapter matvec + fused LayerNorm.
// One block per GRP same-expert tokens; thread o computes C[t][o] for all t.
// ---------------------------------------------------------------------------
__global__ void __launch_bounds__(256)
adapter_grouped(const float* __restrict__ Wexp,
                const float* __restrict__ gamma,
                const float* __restrict__ beta) {
    __shared__ float a_sh[ADP][GRP];   // [k][t]
    __shared__ float c_sh[GRP][ADP];   // [t][o]
    __shared__ int s_tok[GRP];
    __shared__ int s_meta[3];

    const int b = blockIdx.x;
    if (threadIdx.x == 0) {
        int e = 0;
        while (e < NEXP && b >= g_blkoff[e + 1]) e++;
        if (e >= NEXP) {
            s_meta[0] = -1;
        } else {
            int base = g_off[e] + (b - g_blkoff[e]) * GRP;
            s_meta[0] = e;
            s_meta[1] = base;
            s_meta[2] = min(GRP, g_off[e + 1] - base);
        }
    }
    __syncthreads();
    const int e = s_meta[0];
    if (e < 0) return;
    const int base = s_meta[1], cnt = s_meta[2];

    if (threadIdx.x < GRP)
        s_tok[threadIdx.x] = (threadIdx.x < cnt) ? g_perm[base + threadIdx.x] : -1;
    __syncthreads();

    for (int i = threadIdx.x; i < ADP * GRP; i += 256) {
        int k = i >> 4, t = i & (GRP - 1);
        int tok = s_tok[t];
        a_sh[k][t] = (tok >= 0) ? g_A[tok * ADP + k] : 0.0f;
    }
    __syncthreads();

    // matvec: thread o accumulates GRP tokens
    const int o = threadIdx.x;
    float acc[GRP];
#pragma unroll
    for (int t = 0; t < GRP; t++) acc[t] = 0.0f;

    const float4* wr = (const float4*)(Wexp + ((size_t)e * ADP + o) * ADP);
#pragma unroll 4
    for (int k4 = 0; k4 < ADP / 4; k4++) {
        float4 w = wr[k4];
        float wv[4] = {w.x, w.y, w.z, w.w};
#pragma unroll
        for (int j = 0; j < 4; j++) {
            const float4* ap = (const float4*)&a_sh[k4 * 4 + j][0];
#pragma unroll
            for (int t4 = 0; t4 < GRP / 4; t4++) {
                float4 a = ap[t4];
                acc[t4 * 4 + 0] = fmaf(wv[j], a.x, acc[t4 * 4 + 0]);
                acc[t4 * 4 + 1] = fmaf(wv[j], a.y, acc[t4 * 4 + 1]);
                acc[t4 * 4 + 2] = fmaf(wv[j], a.z, acc[t4 * 4 + 2]);
                acc[t4 * 4 + 3] = fmaf(wv[j], a.w, acc[t4 * 4 + 3]);
            }
        }
    }
#pragma unroll
    for (int t = 0; t < GRP; t++) c_sh[t][o] = acc[t];
    __syncthreads();

    // fused LayerNorm: warp w handles tokens w, w+8
    const int warp = threadIdx.x >> 5, lane = threadIdx.x & 31;
    for (int t = warp; t < GRP; t += 8) {
        if (t >= cnt) continue;
        float v[8], s = 0.0f;
#pragma unroll
        for (int j = 0; j < 8; j++) {
            v[j] = c_sh[t][lane + 32 * j];
            s += v[j];
        }
#pragma unroll
        for (int d = 16; d > 0; d >>= 1) s += __shfl_xor_sync(0xffffffffu, s, d);
        float mu = s * (1.0f / ADP);
        float q = 0.0f;
#pragma unroll
        for (int j = 0; j < 8; j++) {
            float dd = v[j] - mu;
            q += dd * dd;
        }
#pragma unroll
        for (int d = 16; d > 0; d >>= 1) q += __shfl_xor_sync(0xffffffffu, q, d);
        float rs = rsqrtf(q * (1.0f / ADP) + 1e-5f);
        int tok = s_tok[t];
#pragma unroll
        for (int j = 0; j < 8; j++) {
            int oo = lane + 32 * j;
            g_AN[tok * ADP + oo] =
                (v[j] - mu) * rs * gamma[e * ADP + oo] + beta[e * ADP + oo];
        }
    }
}

// ---------------------------------------------------------------------------
// Launch
// ---------------------------------------------------------------------------
extern "C" void kernel_launch(void* const* d_in, const int* in_sizes, int n_in,
                              void* d_out, int out_size) {
    const float* x     = (const float*)d_in[0];
    const float* ew    = (const float*)d_in[1];
    const float* W_up  = (const float*)d_in[2];
    const float* W_ad  = (const float*)d_in[3];
    const float* W_exp = (const float*)d_in[4];
    const float* gamma = (const float*)d_in[5];
    const float* beta  = (const float*)d_in[6];
    const float* W_ep  = (const float*)d_in[7];
    const float* W_out = (const float*)d_in[8];
    float* out = (float*)d_out;

    void *pH, *pA;
    cudaGetSymbolAddress(&pH, g_H);
    cudaGetSymbolAddress(&pA, g_A);
    float* H  = (float*)pH;
    float* Aa = (float*)pA;
    void* pAN;
    cudaGetSymbolAddress(&pAN, g_AN);
    float* AN = (float*)pAN;

    // grouping pipeline
    init_kernel<<<1, 32>>>();
    route_kernel<<<(T_TOK + 255) / 256, 256>>>(ew);
    scan_kernel<<<1, 32>>>();
    scatter_kernel<<<(T_TOK + 255) / 256, 256>>>();

    // H = silu(x @ W_up^T)          [T, HID], K = D
    gemm_tf32<0><<<dim3(HID / BN, T_TOK / BM), 256>>>(x, W_up, H, T_TOK, HID, D_EMB);
    // A = H @ W_adapt^T             [T, ADP], K = HID
    gemm_tf32<1><<<dim3(ADP / BN, T_TOK / BM), 256>>>(H, W_ad, Aa, T_TOK, ADP, HID);
    // adapter + LN -> AN (grouped by expert)
    adapter_grouped<<<T_TOK / GRP + NEXP, 256>>>(W_exp, gamma, beta);
    // H += 0.1 * (AN @ W_ep^T)      [T, HID], K = ADP
    gemm_tf32<2><<<dim3(HID / BN, T_TOK / BM), 256>>>(AN, W_ep, H, T_TOK, HID, ADP);
    // out = H @ W_out^T             [T, D], K = HID (fused shared+expert path)
    gemm_tf32<1><<<dim3(D_EMB / BN, T_TOK / BM), 256>>>(H, W_out, out, T_TOK, D_EMB, HID);
}